// round 8
// baseline (speedup 1.0000x reference)
#include <cuda_runtime.h>

// ---------------------------------------------------------------------------
// SymmetricContraction: out[b,c,m] = cubic polynomial in A[b,c,0..8]
// Stage 1 (prep): S[c][t][m] = sum_k Usym[t][m][k] * w_k[c]   (g_S, c-major)
// Stage 2 (main): single fused kernel, native layouts:
//   block = 8 warps; warp w <-> channel c0+w; 64 nodes/block (NBT=2).
//   A tile + out tile staged through smem (coalesced global, odd-stride LDS).
//   S rows: warp-uniform broadcast LDS from per-warp smem table.
// ---------------------------------------------------------------------------

#define NC 128
#define NB 2048
#define NI 9
#define NT 219        // 9 singles + 45 pairs + 165 triples
#define ROWP 12       // padded S row -> 48B
#define NBT 2         // nodes per thread
#define CPB 8         // channels per block (= warps)
#define BPB 64        // nodes per block (32 lanes * NBT)
#define TW  72        // floats per (b, 8-channel) run  = CPB*NI
#define TPAD 73       // padded tile row (odd -> conflict-free)

#define TBLW (NT * ROWP)            // 2628 floats per channel table
#define SM_TBL (CPB * TBLW)         // 21024 floats
#define SM_TILE (BPB * TPAD)        // 4672 floats
#define SMEM_BYTES ((SM_TBL + SM_TILE) * 4)   // 102784 B

#define NROW2 (45 * 9)
#define NROW3 (165 * 9)
#define NROWS (9 + NROW2 + NROW3)

static __device__ float g_S[NC * TBLW];   // ~1.35 MB

// ---------------------------------------------------------------------------
// Kernel 1: fused prep (unchanged — verified)
// ---------------------------------------------------------------------------
__global__ void prep_kernel(
    const float* __restrict__ Us1, const float* __restrict__ Up1, const float* __restrict__ Ud1,
    const float* __restrict__ Us2, const float* __restrict__ Up2, const float* __restrict__ Ud2,
    const float* __restrict__ Us3, const float* __restrict__ Up3, const float* __restrict__ Ud3,
    const float* __restrict__ ws1, const float* __restrict__ ws2, const float* __restrict__ ws3,
    const float* __restrict__ wp1, const float* __restrict__ wp2, const float* __restrict__ wp3,
    const float* __restrict__ wd1, const float* __restrict__ wd2, const float* __restrict__ wd3)
{
    int gid = blockIdx.x * blockDim.x + threadIdx.x;
    if (gid >= NROWS * NC) return;
    int c = gid % NC;
    int row = gid / NC;

    if (row < 9) {
        int t = row;
        float* dst = g_S + c * TBLW + t * ROWP;
        dst[0] = Us1[t] * ws1[c];
#pragma unroll
        for (int m = 0; m < 3; m++) dst[1 + m] = Up1[m * 9 + t] * wp1[c];
#pragma unroll
        for (int m = 0; m < 5; m++) dst[4 + m] = Ud1[m * 9 + t] * wd1[c];
        dst[9] = 0.f; dst[10] = 0.f; dst[11] = 0.f;
        return;
    }

    if (row < 9 + NROW2) {
        int r = row - 9;
        int m = r % 9, tp = r / 9;
        int t = 9 + tp;
        int rem = tp, i = 0, j = 0;
        for (i = 0; i < 9; i++) { int cnt = 9 - i; if (rem < cnt) { j = i + rem; break; } rem -= cnt; }
        float inv = (i == j) ? 0.5f : 1.0f;

        int K; const float* U; const float* w; int mm;
        if (m == 0)      { K = 2; U = Us2; w = ws2; mm = 0; }
        else if (m < 4)  { K = 3; U = Up2; w = wp2; mm = m - 1; }
        else             { K = 4; U = Ud2; w = wd2; mm = m - 4; }

        float s = 0.f;
        for (int k = 0; k < K; k++) {
            float u = U[((mm * 9 + i) * 9 + j) * K + k] + U[((mm * 9 + j) * 9 + i) * K + k];
            s += u * w[k * NC + c];
        }
        float* dst = g_S + c * TBLW + t * ROWP;
        dst[m] = s * inv;
        if (m < 3) dst[9 + m] = 0.f;
        return;
    }

    {
        int r = row - (9 + NROW2);
        int m = r % 9, tp = r / 9;
        int t = 54 + tp;
        int rem = tp, i = 0, j = 0, l = 0;
        for (i = 0; i < 9; i++) { int cnt = (9 - i) * (10 - i) / 2; if (rem < cnt) break; rem -= cnt; }
        for (j = i; j < 9; j++) { int cnt = 9 - j; if (rem < cnt) { l = j + rem; break; } rem -= cnt; }
        float inv;
        if (i == j && j == l)                 inv = 1.0f / 6.0f;
        else if (i == j || j == l || i == l)  inv = 0.5f;
        else                                  inv = 1.0f;

        int K; const float* U; const float* w; int mm;
        if (m == 0)      { K = 5;  U = Us3; w = ws3; mm = 0; }
        else if (m < 4)  { K = 8;  U = Up3; w = wp3; mm = m - 1; }
        else             { K = 10; U = Ud3; w = wd3; mm = m - 4; }

        int P0[6] = { i,i,j,j,l,l }, P1[6] = { j,l,i,l,i,j }, P2i[6] = { l,j,l,i,j,i };
        float s = 0.f;
        for (int k = 0; k < K; k++) {
            float u = 0.f;
#pragma unroll
            for (int p = 0; p < 6; p++)
                u += U[(((mm * 9 + P0[p]) * 9 + P1[p]) * 9 + P2i[p]) * K + k];
            s += u * w[k * NC + c];
        }
        float* dst = g_S + c * TBLW + t * ROWP;
        dst[m] = s * inv;
        if (m < 3) dst[9 + m] = 0.f;
    }
}

// ---------------------------------------------------------------------------
// Kernel 2: fused main. 256 threads = 8 warps (warp <-> channel), NBT=2.
// ---------------------------------------------------------------------------
__device__ __forceinline__ void fma9xN(float acc[NBT][9], const float* __restrict__ row,
                                       const float mN[NBT])
{
    float4 r0 = *reinterpret_cast<const float4*>(row);
    float4 r1 = *reinterpret_cast<const float4*>(row + 4);
    float  r8 = row[8];
#pragma unroll
    for (int n = 0; n < NBT; n++) {
        acc[n][0] = fmaf(r0.x, mN[n], acc[n][0]);
        acc[n][1] = fmaf(r0.y, mN[n], acc[n][1]);
        acc[n][2] = fmaf(r0.z, mN[n], acc[n][2]);
        acc[n][3] = fmaf(r0.w, mN[n], acc[n][3]);
        acc[n][4] = fmaf(r1.x, mN[n], acc[n][4]);
        acc[n][5] = fmaf(r1.y, mN[n], acc[n][5]);
        acc[n][6] = fmaf(r1.z, mN[n], acc[n][6]);
        acc[n][7] = fmaf(r1.w, mN[n], acc[n][7]);
        acc[n][8] = fmaf(r8,  mN[n], acc[n][8]);
    }
}

__global__ __launch_bounds__(256) void sc_main_kernel(
    const float* __restrict__ A, float* __restrict__ out)
{
    extern __shared__ __align__(16) float smem[];
    float* sT = smem;                 // [CPB][TBLW]
    float* sA = smem + SM_TBL;        // [BPB][TPAD], reused for output

    int c0 = blockIdx.x * CPB;
    int b0 = blockIdx.y * BPB;
    int tid = threadIdx.x;
    int w = tid >> 5, lane = tid & 31;

    // ---- fill S tables (coalesced, no divides)
#pragma unroll 1
    for (int cl = 0; cl < CPB; cl++) {
        const float* src = g_S + (c0 + cl) * TBLW;
        float* dst = sT + cl * TBLW;
        for (int idx = tid; idx < TBLW; idx += 256)
            dst[idx] = src[idx];
    }

    // ---- fill A tile: 64 runs of 72 contiguous floats (coalesced)
    for (int v = tid; v < BPB * TW; v += 256) {
        int bl = v / TW, q = v % TW;
        sA[bl * TPAD + q] = A[(b0 + bl) * (NC * NI) + c0 * NI + q];
    }
    __syncthreads();

    // ---- per-thread a-vectors from smem (odd stride 73 -> conflict-free)
    float a[NBT][9];
#pragma unroll
    for (int n = 0; n < NBT; n++) {
        const float* ap = sA + (lane + n * 32) * TPAD + w * NI;
#pragma unroll
        for (int i = 0; i < 9; i++) a[n][i] = ap[i];
    }

    const float* tbl = sT + w * TBLW;

    float acc[NBT][9];
#pragma unroll
    for (int n = 0; n < NBT; n++)
#pragma unroll
        for (int q = 0; q < 9; q++) acc[n][q] = 0.f;

    // ---- degree 1
#pragma unroll
    for (int i = 0; i < 9; i++) {
        float mN[NBT];
#pragma unroll
        for (int n = 0; n < NBT; n++) mN[n] = a[n][i];
        fma9xN(acc, tbl + i * ROWP, mN);
    }

    // ---- degree 2 + 3
    int trow = 54;
#pragma unroll
    for (int i = 0; i < 9; i++) {
#pragma unroll
        for (int j = i; j < 9; j++) {
            int pidx = i * 9 - (i * (i - 1)) / 2 + (j - i);
            float pN[NBT];
#pragma unroll
            for (int n = 0; n < NBT; n++) pN[n] = a[n][i] * a[n][j];
            fma9xN(acc, tbl + (9 + pidx) * ROWP, pN);
#pragma unroll
            for (int l = j; l < 9; l++) {
                float mN[NBT];
#pragma unroll
                for (int n = 0; n < NBT; n++) mN[n] = pN[n] * a[n][l];
                fma9xN(acc, tbl + trow * ROWP, mN);
                trow++;
            }
        }
    }

    // ---- stage results into the tile (a[] fully consumed), then flush
    __syncthreads();
#pragma unroll
    for (int n = 0; n < NBT; n++) {
        float* op = sA + (lane + n * 32) * TPAD + w * NI;
#pragma unroll
        for (int q = 0; q < 9; q++) op[q] = acc[n][q];
    }
    __syncthreads();

    for (int v = tid; v < BPB * TW; v += 256) {
        int bl = v / TW, q = v % TW;
        out[(b0 + bl) * (NC * NI) + c0 * NI + q] = sA[bl * TPAD + q];
    }
}

// ---------------------------------------------------------------------------
// Launch
// ---------------------------------------------------------------------------
extern "C" void kernel_launch(void* const* d_in, const int* in_sizes, int n_in,
                              void* d_out, int out_size)
{
    const float* A = nullptr;
    const float* U[3][3] = {};
    const float* W[3][3] = {};

    int typeorder[3] = { 0, 1, 2 };
    int to_n = 0;
    int w1_idx[3]; int w1_n = 0;

    for (int idx = 0; idx < n_in; idx++) {
        int s = in_sizes[idx];
        const float* p = (const float*)d_in[idx];
        switch (s) {
            case NB * NC * NI: A = p; break;
            case 9:     U[0][0] = p; break;
            case 162:   U[0][1] = p; break;
            case 3645:  U[0][2] = p; break;
            case 27:    U[1][0] = p; break;
            case 729:   U[1][1] = p; break;
            case 17496: U[1][2] = p; break;
            case 45:    U[2][0] = p; break;
            case 1620:  U[2][1] = p; break;
            case 36450: U[2][2] = p; break;
            case 256:   W[0][1] = p; if (to_n < 3) typeorder[to_n++] = 0; break;
            case 384:   W[1][1] = p; if (to_n < 3) typeorder[to_n++] = 1; break;
            case 512:   W[2][1] = p; if (to_n < 3) typeorder[to_n++] = 2; break;
            case 640:   W[0][2] = p; break;
            case 1024:  W[1][2] = p; break;
            case 1280:  W[2][2] = p; break;
            case 128:   if (w1_n < 3) w1_idx[w1_n++] = idx; break;
            default: break;
        }
    }
    for (int q = 0; q < 3 && q < w1_n; q++)
        W[typeorder[q]][0] = (const float*)d_in[w1_idx[q]];

    // allow >48KB dynamic smem (idempotent; not an allocation)
    static bool attr_done = false;
    if (!attr_done) {
        cudaFuncSetAttribute(sc_main_kernel,
                             cudaFuncAttributeMaxDynamicSharedMemorySize, SMEM_BYTES);
        attr_done = true;
    }

    // Stage 1: prep
    {
        int jobs = NROWS * NC;
        prep_kernel<<<(jobs + 255) / 256, 256>>>(
            U[0][0], U[1][0], U[2][0],
            U[0][1], U[1][1], U[2][1],
            U[0][2], U[1][2], U[2][2],
            W[0][0], W[0][1], W[0][2],
            W[1][0], W[1][1], W[1][2],
            W[2][0], W[2][1], W[2][2]);
    }

    // Stage 2: fused main
    {
        dim3 grid(NC / CPB, NB / BPB);   // (16, 32)
        sc_main_kernel<<<grid, 256, SMEM_BYTES>>>(A, (float*)d_out);
    }
}

// round 9
// speedup vs baseline: 1.0990x; 1.0990x over previous
#include <cuda_runtime.h>

// ---------------------------------------------------------------------------
// SymmetricContraction: out[b,c,m] = cubic polynomial in A[b,c,0..8]
// Launch 1 (pre):  [blocks 0..1023]   trA: A[b][c][9] -> At[c][b][12], MLP=9
//                  [blocks 1024..]    prep: S[c][t][m] = sum_k Usym*w
// Launch 2 (main): Ot[c][b][12] = sum_t S[c][t][:] * mono_t(At[c][b][:])
// Launch 3 (trO):  Ot -> out[b][c][9], vector reads + smem-staged writes
// ---------------------------------------------------------------------------

#define NC 128
#define NB 2048
#define NI 9
#define NIP 12
#define NT 219
#define ROWP 12
#define NBT 2
#define BLK 128

#define NROW2 (45 * 9)
#define NROW3 (165 * 9)
#define NROWS (9 + NROW2 + NROW3)           // 1899
#define PREP_BLOCKS ((NROWS * NC + 255) / 256)   // 950
#define TRA_BLOCKS  (NC * NB / 256)              // 1024

static __device__ float g_S[NC * NT * ROWP];
static __device__ float g_At[NC * NB * NIP];
static __device__ float g_Ot[NC * NB * NIP];

// ---------------------------------------------------------------------------
// prep body (verified logic, unchanged)
// ---------------------------------------------------------------------------
__device__ void prep_body(int gid,
    const float* __restrict__ Us1, const float* __restrict__ Up1, const float* __restrict__ Ud1,
    const float* __restrict__ Us2, const float* __restrict__ Up2, const float* __restrict__ Ud2,
    const float* __restrict__ Us3, const float* __restrict__ Up3, const float* __restrict__ Ud3,
    const float* __restrict__ ws1, const float* __restrict__ ws2, const float* __restrict__ ws3,
    const float* __restrict__ wp1, const float* __restrict__ wp2, const float* __restrict__ wp3,
    const float* __restrict__ wd1, const float* __restrict__ wd2, const float* __restrict__ wd3)
{
    if (gid >= NROWS * NC) return;
    int c = gid % NC;
    int row = gid / NC;

    if (row < 9) {
        int t = row;
        float* dst = g_S + (c * NT + t) * ROWP;
        dst[0] = Us1[t] * ws1[c];
#pragma unroll
        for (int m = 0; m < 3; m++) dst[1 + m] = Up1[m * 9 + t] * wp1[c];
#pragma unroll
        for (int m = 0; m < 5; m++) dst[4 + m] = Ud1[m * 9 + t] * wd1[c];
        dst[9] = 0.f; dst[10] = 0.f; dst[11] = 0.f;
        return;
    }

    if (row < 9 + NROW2) {
        int r = row - 9;
        int m = r % 9, tp = r / 9;
        int t = 9 + tp;
        int rem = tp, i = 0, j = 0;
        for (i = 0; i < 9; i++) { int cnt = 9 - i; if (rem < cnt) { j = i + rem; break; } rem -= cnt; }
        float inv = (i == j) ? 0.5f : 1.0f;

        int K; const float* U; const float* w; int mm;
        if (m == 0)      { K = 2; U = Us2; w = ws2; mm = 0; }
        else if (m < 4)  { K = 3; U = Up2; w = wp2; mm = m - 1; }
        else             { K = 4; U = Ud2; w = wd2; mm = m - 4; }

        float s = 0.f;
        for (int k = 0; k < K; k++) {
            float u = U[((mm * 9 + i) * 9 + j) * K + k] + U[((mm * 9 + j) * 9 + i) * K + k];
            s += u * w[k * NC + c];
        }
        float* dst = g_S + (c * NT + t) * ROWP;
        dst[m] = s * inv;
        if (m < 3) dst[9 + m] = 0.f;
        return;
    }

    {
        int r = row - (9 + NROW2);
        int m = r % 9, tp = r / 9;
        int t = 54 + tp;
        int rem = tp, i = 0, j = 0, l = 0;
        for (i = 0; i < 9; i++) { int cnt = (9 - i) * (10 - i) / 2; if (rem < cnt) break; rem -= cnt; }
        for (j = i; j < 9; j++) { int cnt = 9 - j; if (rem < cnt) { l = j + rem; break; } rem -= cnt; }
        float inv;
        if (i == j && j == l)                 inv = 1.0f / 6.0f;
        else if (i == j || j == l || i == l)  inv = 0.5f;
        else                                  inv = 1.0f;

        int K; const float* U; const float* w; int mm;
        if (m == 0)      { K = 5;  U = Us3; w = ws3; mm = 0; }
        else if (m < 4)  { K = 8;  U = Up3; w = wp3; mm = m - 1; }
        else             { K = 10; U = Ud3; w = wd3; mm = m - 4; }

        int P0[6] = { i,i,j,j,l,l }, P1[6] = { j,l,i,l,i,j }, P2i[6] = { l,j,l,i,j,i };
        float s = 0.f;
        for (int k = 0; k < K; k++) {
            float u = 0.f;
#pragma unroll
            for (int p = 0; p < 6; p++)
                u += U[(((mm * 9 + P0[p]) * 9 + P1[p]) * 9 + P2i[p]) * K + k];
            s += u * w[k * NC + c];
        }
        float* dst = g_S + (c * NT + t) * ROWP;
        dst[m] = s * inv;
        if (m < 3) dst[9 + m] = 0.f;
    }
}

// ---------------------------------------------------------------------------
// Launch 1: fused trA + prep.
// trA: thread <-> (c,b), b lane-fastest. 9 independent LDG (MLP=9),
//      3 STG.128 -> warp writes 1536B contiguous to g_At.
// ---------------------------------------------------------------------------
__global__ __launch_bounds__(256) void pre_kernel(
    const float* __restrict__ A,
    const float* __restrict__ Us1, const float* __restrict__ Up1, const float* __restrict__ Ud1,
    const float* __restrict__ Us2, const float* __restrict__ Up2, const float* __restrict__ Ud2,
    const float* __restrict__ Us3, const float* __restrict__ Up3, const float* __restrict__ Ud3,
    const float* __restrict__ ws1, const float* __restrict__ ws2, const float* __restrict__ ws3,
    const float* __restrict__ wp1, const float* __restrict__ wp2, const float* __restrict__ wp3,
    const float* __restrict__ wd1, const float* __restrict__ wd2, const float* __restrict__ wd3)
{
    if (blockIdx.x < TRA_BLOCKS) {
        int cb = blockIdx.x * 256 + threadIdx.x;   // c*NB + b, b fastest
        int b = cb & (NB - 1);
        int c = cb >> 11;
        const float* src = A + (b * NC + c) * NI;
        float v[9];
#pragma unroll
        for (int i = 0; i < 9; i++) v[i] = __ldg(src + i);   // 9 independent loads
        float4* dst = reinterpret_cast<float4*>(g_At + cb * NIP);
        dst[0] = make_float4(v[0], v[1], v[2], v[3]);
        dst[1] = make_float4(v[4], v[5], v[6], v[7]);
        dst[2] = make_float4(v[8], 0.f, 0.f, 0.f);
    } else {
        int gid = (blockIdx.x - TRA_BLOCKS) * 256 + threadIdx.x;
        prep_body(gid, Us1, Up1, Ud1, Us2, Up2, Ud2, Us3, Up3, Ud3,
                  ws1, ws2, ws3, wp1, wp2, wp3, wd1, wd2, wd3);
    }
}

// ---------------------------------------------------------------------------
// Launch 2: main (verbatim R7 — measured <11.4us)
// ---------------------------------------------------------------------------
__device__ __forceinline__ void fma9xN(float acc[NBT][9], const float* __restrict__ row,
                                       const float mN[NBT])
{
    float4 r0 = *reinterpret_cast<const float4*>(row);
    float4 r1 = *reinterpret_cast<const float4*>(row + 4);
    float  r8 = row[8];
#pragma unroll
    for (int n = 0; n < NBT; n++) {
        acc[n][0] = fmaf(r0.x, mN[n], acc[n][0]);
        acc[n][1] = fmaf(r0.y, mN[n], acc[n][1]);
        acc[n][2] = fmaf(r0.z, mN[n], acc[n][2]);
        acc[n][3] = fmaf(r0.w, mN[n], acc[n][3]);
        acc[n][4] = fmaf(r1.x, mN[n], acc[n][4]);
        acc[n][5] = fmaf(r1.y, mN[n], acc[n][5]);
        acc[n][6] = fmaf(r1.z, mN[n], acc[n][6]);
        acc[n][7] = fmaf(r1.w, mN[n], acc[n][7]);
        acc[n][8] = fmaf(r8,  mN[n], acc[n][8]);
    }
}

__global__ __launch_bounds__(BLK) void sc_main_kernel()
{
    __shared__ __align__(16) float sS[NT * ROWP];

    int c = blockIdx.x;
    const float* gS = g_S + c * NT * ROWP;
    for (int idx = threadIdx.x; idx < NT * ROWP; idx += BLK)
        sS[idx] = gS[idx];
    __syncthreads();

    int bbase = blockIdx.y * (BLK * NBT) + threadIdx.x;

    float a[NBT][9];
#pragma unroll
    for (int n = 0; n < NBT; n++) {
        const float4* Ap = reinterpret_cast<const float4*>(
            g_At + (c * NB + bbase + n * BLK) * NIP);
        float4 v0 = Ap[0], v1 = Ap[1], v2 = Ap[2];
        a[n][0] = v0.x; a[n][1] = v0.y; a[n][2] = v0.z; a[n][3] = v0.w;
        a[n][4] = v1.x; a[n][5] = v1.y; a[n][6] = v1.z; a[n][7] = v1.w;
        a[n][8] = v2.x;
    }

    float acc[NBT][9];
#pragma unroll
    for (int n = 0; n < NBT; n++)
#pragma unroll
        for (int q = 0; q < 9; q++) acc[n][q] = 0.f;

#pragma unroll
    for (int i = 0; i < 9; i++) {
        float mN[NBT];
#pragma unroll
        for (int n = 0; n < NBT; n++) mN[n] = a[n][i];
        fma9xN(acc, sS + i * ROWP, mN);
    }

    int trow = 54;
#pragma unroll
    for (int i = 0; i < 9; i++) {
#pragma unroll
        for (int j = i; j < 9; j++) {
            int pidx = i * 9 - (i * (i - 1)) / 2 + (j - i);
            float pN[NBT];
#pragma unroll
            for (int n = 0; n < NBT; n++) pN[n] = a[n][i] * a[n][j];
            fma9xN(acc, sS + (9 + pidx) * ROWP, pN);
#pragma unroll
            for (int l = j; l < 9; l++) {
                float mN[NBT];
#pragma unroll
                for (int n = 0; n < NBT; n++) mN[n] = pN[n] * a[n][l];
                fma9xN(acc, sS + trow * ROWP, mN);
                trow++;
            }
        }
    }

#pragma unroll
    for (int n = 0; n < NBT; n++) {
        float4* op = reinterpret_cast<float4*>(
            g_Ot + (c * NB + bbase + n * BLK) * NIP);
        op[0] = make_float4(acc[n][0], acc[n][1], acc[n][2], acc[n][3]);
        op[1] = make_float4(acc[n][4], acc[n][5], acc[n][6], acc[n][7]);
        op[2] = make_float4(acc[n][8], 0.f, 0.f, 0.f);
    }
}

// ---------------------------------------------------------------------------
// Launch 3: trO. Thread <-> (b,c), c lane-fastest (256 bc per block).
// Reads: 3 LDG.128 from g_Ot (MLP=3). Stage 9 floats in smem (stride 9,
// coprime to 32 -> conflict-free), then flat coalesced copy to out.
// ---------------------------------------------------------------------------
__global__ __launch_bounds__(256) void trO_kernel(float* __restrict__ out)
{
    __shared__ float tile[256 * NI];    // 9216 B

    int bcbase = blockIdx.x * 256;
    int bc = bcbase + threadIdx.x;      // b*NC + c
    int c = bc & (NC - 1);
    int b = bc >> 7;

    const float4* src = reinterpret_cast<const float4*>(g_Ot + (c * NB + b) * NIP);
    float4 v0 = src[0], v1 = src[1], v2 = src[2];   // 3 independent loads

    float* trow = tile + threadIdx.x * NI;
    trow[0] = v0.x; trow[1] = v0.y; trow[2] = v0.z; trow[3] = v0.w;
    trow[4] = v1.x; trow[5] = v1.y; trow[6] = v1.z; trow[7] = v1.w;
    trow[8] = v2.x;
    __syncthreads();

    float* dst = out + bcbase * NI;
#pragma unroll
    for (int k = 0; k < NI; k++)
        dst[threadIdx.x + k * 256] = tile[threadIdx.x + k * 256];
}

// ---------------------------------------------------------------------------
// Launch
// ---------------------------------------------------------------------------
extern "C" void kernel_launch(void* const* d_in, const int* in_sizes, int n_in,
                              void* d_out, int out_size)
{
    const float* A = nullptr;
    const float* U[3][3] = {};
    const float* W[3][3] = {};

    int typeorder[3] = { 0, 1, 2 };
    int to_n = 0;
    int w1_idx[3]; int w1_n = 0;

    for (int idx = 0; idx < n_in; idx++) {
        int s = in_sizes[idx];
        const float* p = (const float*)d_in[idx];
        switch (s) {
            case NB * NC * NI: A = p; break;
            case 9:     U[0][0] = p; break;
            case 162:   U[0][1] = p; break;
            case 3645:  U[0][2] = p; break;
            case 27:    U[1][0] = p; break;
            case 729:   U[1][1] = p; break;
            case 17496: U[1][2] = p; break;
            case 45:    U[2][0] = p; break;
            case 1620:  U[2][1] = p; break;
            case 36450: U[2][2] = p; break;
            case 256:   W[0][1] = p; if (to_n < 3) typeorder[to_n++] = 0; break;
            case 384:   W[1][1] = p; if (to_n < 3) typeorder[to_n++] = 1; break;
            case 512:   W[2][1] = p; if (to_n < 3) typeorder[to_n++] = 2; break;
            case 640:   W[0][2] = p; break;
            case 1024:  W[1][2] = p; break;
            case 1280:  W[2][2] = p; break;
            case 128:   if (w1_n < 3) w1_idx[w1_n++] = idx; break;
            default: break;
        }
    }
    for (int q = 0; q < 3 && q < w1_n; q++)
        W[typeorder[q]][0] = (const float*)d_in[w1_idx[q]];

    // Launch 1: fused trA + prep
    pre_kernel<<<TRA_BLOCKS + PREP_BLOCKS, 256>>>(
        A,
        U[0][0], U[1][0], U[2][0],
        U[0][1], U[1][1], U[2][1],
        U[0][2], U[1][2], U[2][2],
        W[0][0], W[0][1], W[0][2],
        W[1][0], W[1][1], W[1][2],
        W[2][0], W[2][1], W[2][2]);

    // Launch 2: main
    {
        dim3 grid(NC, NB / (BLK * NBT));
        sc_main_kernel<<<grid, BLK>>>();
    }

    // Launch 3: trO
    trO_kernel<<<NB * NC / 256, 256>>>((float*)d_out);
}

// round 10
// speedup vs baseline: 1.2308x; 1.1199x over previous
#include <cuda_runtime.h>

// ---------------------------------------------------------------------------
// SymmetricContraction: out[b,c,m] = cubic polynomial in A[b,c,0..8]
// Launch 1 (pre):  [blocks 0..255]   trA: A -> At via 32x32 smem tile,
//                                    coalesced on BOTH global sides
//                  [blocks 256..]    prep: S[c][t][m] = sum_k Usym*w
// Launch 2 (main): Ot[c][b][12] = sum_t S[c][t][:] * mono_t(At[c][b][:])
// Launch 3 (trO):  Ot -> out, mirrored 32x32 smem tile (both sides coalesced)
// ---------------------------------------------------------------------------

#define NC 128
#define NB 2048
#define NI 9
#define NIP 12
#define NT 219
#define ROWP 12
#define NBT 2
#define BLK 128

#define NROW2 (45 * 9)
#define NROW3 (165 * 9)
#define NROWS (9 + NROW2 + NROW3)                  // 1899
#define PREP_BLOCKS ((NROWS * NC + 255) / 256)     // 950

#define TRB 32                    // b per transpose tile
#define TRC 32                    // c per transpose tile
#define TP  289                   // smem row stride (32*9 + 1, odd)
#define TRA_TILES ((NB / TRB) * (NC / TRC))        // 64 * 4 = 256
#define TILE_WORDS (TRB * TRC * NI)                // 9216

static __device__ float g_S[NC * NT * ROWP];
static __device__ float g_At[NC * NB * NIP];
static __device__ float g_Ot[NC * NB * NIP];

// ---------------------------------------------------------------------------
// prep body (verified logic, unchanged)
// ---------------------------------------------------------------------------
__device__ void prep_body(int gid,
    const float* __restrict__ Us1, const float* __restrict__ Up1, const float* __restrict__ Ud1,
    const float* __restrict__ Us2, const float* __restrict__ Up2, const float* __restrict__ Ud2,
    const float* __restrict__ Us3, const float* __restrict__ Up3, const float* __restrict__ Ud3,
    const float* __restrict__ ws1, const float* __restrict__ ws2, const float* __restrict__ ws3,
    const float* __restrict__ wp1, const float* __restrict__ wp2, const float* __restrict__ wp3,
    const float* __restrict__ wd1, const float* __restrict__ wd2, const float* __restrict__ wd3)
{
    if (gid >= NROWS * NC) return;
    int c = gid % NC;
    int row = gid / NC;

    if (row < 9) {
        int t = row;
        float* dst = g_S + (c * NT + t) * ROWP;
        dst[0] = Us1[t] * ws1[c];
#pragma unroll
        for (int m = 0; m < 3; m++) dst[1 + m] = Up1[m * 9 + t] * wp1[c];
#pragma unroll
        for (int m = 0; m < 5; m++) dst[4 + m] = Ud1[m * 9 + t] * wd1[c];
        dst[9] = 0.f; dst[10] = 0.f; dst[11] = 0.f;
        return;
    }

    if (row < 9 + NROW2) {
        int r = row - 9;
        int m = r % 9, tp = r / 9;
        int t = 9 + tp;
        int rem = tp, i = 0, j = 0;
        for (i = 0; i < 9; i++) { int cnt = 9 - i; if (rem < cnt) { j = i + rem; break; } rem -= cnt; }
        float inv = (i == j) ? 0.5f : 1.0f;

        int K; const float* U; const float* w; int mm;
        if (m == 0)      { K = 2; U = Us2; w = ws2; mm = 0; }
        else if (m < 4)  { K = 3; U = Up2; w = wp2; mm = m - 1; }
        else             { K = 4; U = Ud2; w = wd2; mm = m - 4; }

        float s = 0.f;
        for (int k = 0; k < K; k++) {
            float u = U[((mm * 9 + i) * 9 + j) * K + k] + U[((mm * 9 + j) * 9 + i) * K + k];
            s += u * w[k * NC + c];
        }
        float* dst = g_S + (c * NT + t) * ROWP;
        dst[m] = s * inv;
        if (m < 3) dst[9 + m] = 0.f;
        return;
    }

    {
        int r = row - (9 + NROW2);
        int m = r % 9, tp = r / 9;
        int t = 54 + tp;
        int rem = tp, i = 0, j = 0, l = 0;
        for (i = 0; i < 9; i++) { int cnt = (9 - i) * (10 - i) / 2; if (rem < cnt) break; rem -= cnt; }
        for (j = i; j < 9; j++) { int cnt = 9 - j; if (rem < cnt) { l = j + rem; break; } rem -= cnt; }
        float inv;
        if (i == j && j == l)                 inv = 1.0f / 6.0f;
        else if (i == j || j == l || i == l)  inv = 0.5f;
        else                                  inv = 1.0f;

        int K; const float* U; const float* w; int mm;
        if (m == 0)      { K = 5;  U = Us3; w = ws3; mm = 0; }
        else if (m < 4)  { K = 8;  U = Up3; w = wp3; mm = m - 1; }
        else             { K = 10; U = Ud3; w = wd3; mm = m - 4; }

        int P0[6] = { i,i,j,j,l,l }, P1[6] = { j,l,i,l,i,j }, P2i[6] = { l,j,l,i,j,i };
        float s = 0.f;
        for (int k = 0; k < K; k++) {
            float u = 0.f;
#pragma unroll
            for (int p = 0; p < 6; p++)
                u += U[(((mm * 9 + P0[p]) * 9 + P1[p]) * 9 + P2i[p]) * K + k];
            s += u * w[k * NC + c];
        }
        float* dst = g_S + (c * NT + t) * ROWP;
        dst[m] = s * inv;
        if (m < 3) dst[9 + m] = 0.f;
    }
}

// ---------------------------------------------------------------------------
// Launch 1: fused trA (tiled, both-sides coalesced) + prep.
// ---------------------------------------------------------------------------
__global__ __launch_bounds__(256) void pre_kernel(
    const float* __restrict__ A,
    const float* __restrict__ Us1, const float* __restrict__ Up1, const float* __restrict__ Ud1,
    const float* __restrict__ Us2, const float* __restrict__ Up2, const float* __restrict__ Ud2,
    const float* __restrict__ Us3, const float* __restrict__ Up3, const float* __restrict__ Ud3,
    const float* __restrict__ ws1, const float* __restrict__ ws2, const float* __restrict__ ws3,
    const float* __restrict__ wp1, const float* __restrict__ wp2, const float* __restrict__ wp3,
    const float* __restrict__ wd1, const float* __restrict__ wd2, const float* __restrict__ wd3)
{
    __shared__ float tile[TRB * TP];    // ~37 KB

    if (blockIdx.x < TRA_TILES) {
        int bt = blockIdx.x >> 2;            // 64 b-tiles
        int ct = blockIdx.x & 3;             // 4 c-tiles
        int b0 = bt * TRB, c0 = ct * TRC;
        int tid = threadIdx.x;

        // Phase 1: flat coalesced reads of A; each b-row = 288 contiguous words
#pragma unroll
        for (int v = tid; v < TILE_WORDS; v += 256) {
            int b = v / (TRC * NI), q = v - b * (TRC * NI);
            tile[b * TP + q] = A[(b0 + b) * (NC * NI) + c0 * NI + q];
        }
        __syncthreads();

        // Phase 2: thread <-> (c,b), b lane-fastest -> 1536B contiguous/warp
#pragma unroll
        for (int it = 0; it < (TRB * TRC) / 256; it++) {
            int pair = it * 256 + tid;
            int cc = pair >> 5, b = pair & 31;
            const float* src = tile + b * TP + cc * NI;
            float4* dst = reinterpret_cast<float4*>(
                g_At + ((c0 + cc) * NB + b0 + b) * NIP);
            dst[0] = make_float4(src[0], src[1], src[2], src[3]);
            dst[1] = make_float4(src[4], src[5], src[6], src[7]);
            dst[2] = make_float4(src[8], 0.f, 0.f, 0.f);
        }
    } else {
        int gid = (blockIdx.x - TRA_TILES) * 256 + threadIdx.x;
        prep_body(gid, Us1, Up1, Ud1, Us2, Up2, Ud2, Us3, Up3, Ud3,
                  ws1, ws2, ws3, wp1, wp2, wp3, wd1, wd2, wd3);
    }
}

// ---------------------------------------------------------------------------
// Launch 2: main (verbatim — at its FMA floor)
// ---------------------------------------------------------------------------
__device__ __forceinline__ void fma9xN(float acc[NBT][9], const float* __restrict__ row,
                                       const float mN[NBT])
{
    float4 r0 = *reinterpret_cast<const float4*>(row);
    float4 r1 = *reinterpret_cast<const float4*>(row + 4);
    float  r8 = row[8];
#pragma unroll
    for (int n = 0; n < NBT; n++) {
        acc[n][0] = fmaf(r0.x, mN[n], acc[n][0]);
        acc[n][1] = fmaf(r0.y, mN[n], acc[n][1]);
        acc[n][2] = fmaf(r0.z, mN[n], acc[n][2]);
        acc[n][3] = fmaf(r0.w, mN[n], acc[n][3]);
        acc[n][4] = fmaf(r1.x, mN[n], acc[n][4]);
        acc[n][5] = fmaf(r1.y, mN[n], acc[n][5]);
        acc[n][6] = fmaf(r1.z, mN[n], acc[n][6]);
        acc[n][7] = fmaf(r1.w, mN[n], acc[n][7]);
        acc[n][8] = fmaf(r8,  mN[n], acc[n][8]);
    }
}

__global__ __launch_bounds__(BLK) void sc_main_kernel()
{
    __shared__ __align__(16) float sS[NT * ROWP];

    int c = blockIdx.x;
    const float* gS = g_S + c * NT * ROWP;
    for (int idx = threadIdx.x; idx < NT * ROWP; idx += BLK)
        sS[idx] = gS[idx];
    __syncthreads();

    int bbase = blockIdx.y * (BLK * NBT) + threadIdx.x;

    float a[NBT][9];
#pragma unroll
    for (int n = 0; n < NBT; n++) {
        const float4* Ap = reinterpret_cast<const float4*>(
            g_At + (c * NB + bbase + n * BLK) * NIP);
        float4 v0 = Ap[0], v1 = Ap[1], v2 = Ap[2];
        a[n][0] = v0.x; a[n][1] = v0.y; a[n][2] = v0.z; a[n][3] = v0.w;
        a[n][4] = v1.x; a[n][5] = v1.y; a[n][6] = v1.z; a[n][7] = v1.w;
        a[n][8] = v2.x;
    }

    float acc[NBT][9];
#pragma unroll
    for (int n = 0; n < NBT; n++)
#pragma unroll
        for (int q = 0; q < 9; q++) acc[n][q] = 0.f;

#pragma unroll
    for (int i = 0; i < 9; i++) {
        float mN[NBT];
#pragma unroll
        for (int n = 0; n < NBT; n++) mN[n] = a[n][i];
        fma9xN(acc, sS + i * ROWP, mN);
    }

    int trow = 54;
#pragma unroll
    for (int i = 0; i < 9; i++) {
#pragma unroll
        for (int j = i; j < 9; j++) {
            int pidx = i * 9 - (i * (i - 1)) / 2 + (j - i);
            float pN[NBT];
#pragma unroll
            for (int n = 0; n < NBT; n++) pN[n] = a[n][i] * a[n][j];
            fma9xN(acc, sS + (9 + pidx) * ROWP, pN);
#pragma unroll
            for (int l = j; l < 9; l++) {
                float mN[NBT];
#pragma unroll
                for (int n = 0; n < NBT; n++) mN[n] = pN[n] * a[n][l];
                fma9xN(acc, sS + trow * ROWP, mN);
                trow++;
            }
        }
    }

#pragma unroll
    for (int n = 0; n < NBT; n++) {
        float4* op = reinterpret_cast<float4*>(
            g_Ot + (c * NB + bbase + n * BLK) * NIP);
        op[0] = make_float4(acc[n][0], acc[n][1], acc[n][2], acc[n][3]);
        op[1] = make_float4(acc[n][4], acc[n][5], acc[n][6], acc[n][7]);
        op[2] = make_float4(acc[n][8], 0.f, 0.f, 0.f);
    }
}

// ---------------------------------------------------------------------------
// Launch 3: trO — mirror of trA tile (both sides coalesced).
// ---------------------------------------------------------------------------
__global__ __launch_bounds__(256) void trO_kernel(float* __restrict__ out)
{
    __shared__ float tile[TRB * TP];

    int bt = blockIdx.x >> 2;
    int ct = blockIdx.x & 3;
    int b0 = bt * TRB, c0 = ct * TRC;
    int tid = threadIdx.x;

    // Phase 1: thread <-> (c,b), b lane-fastest -> coalesced 1536B warp reads
#pragma unroll
    for (int it = 0; it < (TRB * TRC) / 256; it++) {
        int pair = it * 256 + tid;
        int cc = pair >> 5, b = pair & 31;
        const float4* src = reinterpret_cast<const float4*>(
            g_Ot + ((c0 + cc) * NB + b0 + b) * NIP);
        float4 v0 = src[0], v1 = src[1], v2 = src[2];
        float* t = tile + b * TP + cc * NI;
        t[0] = v0.x; t[1] = v0.y; t[2] = v0.z; t[3] = v0.w;
        t[4] = v1.x; t[5] = v1.y; t[6] = v1.z; t[7] = v1.w;
        t[8] = v2.x;
    }
    __syncthreads();

    // Phase 2: flat coalesced writes; each b-row = 288 contiguous words
#pragma unroll
    for (int v = tid; v < TILE_WORDS; v += 256) {
        int b = v / (TRC * NI), q = v - b * (TRC * NI);
        out[(b0 + b) * (NC * NI) + c0 * NI + q] = tile[b * TP + q];
    }
}

// ---------------------------------------------------------------------------
// Launch
// ---------------------------------------------------------------------------
extern "C" void kernel_launch(void* const* d_in, const int* in_sizes, int n_in,
                              void* d_out, int out_size)
{
    const float* A = nullptr;
    const float* U[3][3] = {};
    const float* W[3][3] = {};

    int typeorder[3] = { 0, 1, 2 };
    int to_n = 0;
    int w1_idx[3]; int w1_n = 0;

    for (int idx = 0; idx < n_in; idx++) {
        int s = in_sizes[idx];
        const float* p = (const float*)d_in[idx];
        switch (s) {
            case NB * NC * NI: A = p; break;
            case 9:     U[0][0] = p; break;
            case 162:   U[0][1] = p; break;
            case 3645:  U[0][2] = p; break;
            case 27:    U[1][0] = p; break;
            case 729:   U[1][1] = p; break;
            case 17496: U[1][2] = p; break;
            case 45:    U[2][0] = p; break;
            case 1620:  U[2][1] = p; break;
            case 36450: U[2][2] = p; break;
            case 256:   W[0][1] = p; if (to_n < 3) typeorder[to_n++] = 0; break;
            case 384:   W[1][1] = p; if (to_n < 3) typeorder[to_n++] = 1; break;
            case 512:   W[2][1] = p; if (to_n < 3) typeorder[to_n++] = 2; break;
            case 640:   W[0][2] = p; break;
            case 1024:  W[1][2] = p; break;
            case 1280:  W[2][2] = p; break;
            case 128:   if (w1_n < 3) w1_idx[w1_n++] = idx; break;
            default: break;
        }
    }
    for (int q = 0; q < 3 && q < w1_n; q++)
        W[typeorder[q]][0] = (const float*)d_in[w1_idx[q]];

    // Launch 1: fused trA + prep
    pre_kernel<<<TRA_TILES + PREP_BLOCKS, 256>>>(
        A,
        U[0][0], U[1][0], U[2][0],
        U[0][1], U[1][1], U[2][1],
        U[0][2], U[1][2], U[2][2],
        W[0][0], W[0][1], W[0][2],
        W[1][0], W[1][1], W[1][2],
        W[2][0], W[2][1], W[2][2]);

    // Launch 2: main
    {
        dim3 grid(NC, NB / (BLK * NBT));
        sc_main_kernel<<<grid, BLK>>>();
    }

    // Launch 3: trO
    trO_kernel<<<TRA_TILES, 256>>>((float*)d_out);
}

// round 11
// speedup vs baseline: 1.2338x; 1.0024x over previous
#include <cuda_runtime.h>

// ---------------------------------------------------------------------------
// SymmetricContraction: out[b,c,m] = cubic polynomial in A[b,c,0..8]
// Launch 1 (pre):  [blocks 0..255]    trA: A -> At via 32x32 smem tile
//                  [blocks 256..]     prep v2: per block, 2 (t,m) rows:
//                     Phase A: Usym[row][k] computed ONCE into smem
//                     Phase B: S[c][t][m] = sum_k Usym[k] * w[k][c] (coalesced)
// Launch 2 (main): Ot[c][b][12] = sum_t S[c][t][:] * mono_t(At[c][b][:])
// Launch 3 (trO):  Ot -> out, mirrored 32x32 smem tile
// ---------------------------------------------------------------------------

#define NC 128
#define NB 2048
#define NI 9
#define NIP 12
#define NT 219
#define ROWP 12
#define NBT 2
#define BLK 128

#define NJOBS (NT * 9)                             // 1971 (t,m) scalar rows
#define RPB 2                                      // job rows per prep block
#define PREP_BLOCKS ((NJOBS + RPB - 1) / RPB)      // 986

#define TRB 32
#define TRC 32
#define TP  289                                    // 32*9+1, odd
#define TRA_TILES ((NB / TRB) * (NC / TRC))        // 256
#define TILE_WORDS (TRB * TRC * NI)                // 9216

static __device__ float g_S[NC * NT * ROWP];
static __device__ float g_At[NC * NB * NIP];
static __device__ float g_Ot[NC * NB * NIP];

// ---------------------------------------------------------------------------
// Launch 1: fused trA + prep-v2
// ---------------------------------------------------------------------------
__global__ __launch_bounds__(256) void pre_kernel(
    const float* __restrict__ A,
    const float* __restrict__ Us1, const float* __restrict__ Up1, const float* __restrict__ Ud1,
    const float* __restrict__ Us2, const float* __restrict__ Up2, const float* __restrict__ Ud2,
    const float* __restrict__ Us3, const float* __restrict__ Up3, const float* __restrict__ Ud3,
    const float* __restrict__ ws1, const float* __restrict__ ws2, const float* __restrict__ ws3,
    const float* __restrict__ wp1, const float* __restrict__ wp2, const float* __restrict__ wp3,
    const float* __restrict__ wd1, const float* __restrict__ wd2, const float* __restrict__ wd3)
{
    if (blockIdx.x < TRA_TILES) {
        // ---------------- trA tile (verified R10) ----------------
        __shared__ float tile[TRB * TP];
        int bt = blockIdx.x >> 2;
        int ct = blockIdx.x & 3;
        int b0 = bt * TRB, c0 = ct * TRC;
        int tid = threadIdx.x;

#pragma unroll
        for (int v = tid; v < TILE_WORDS; v += 256) {
            int b = v / (TRC * NI), q = v - b * (TRC * NI);
            tile[b * TP + q] = A[(b0 + b) * (NC * NI) + c0 * NI + q];
        }
        __syncthreads();

#pragma unroll
        for (int it = 0; it < (TRB * TRC) / 256; it++) {
            int pair = it * 256 + tid;
            int cc = pair >> 5, b = pair & 31;
            const float* src = tile + b * TP + cc * NI;
            float4* dst = reinterpret_cast<float4*>(
                g_At + ((c0 + cc) * NB + b0 + b) * NIP);
            dst[0] = make_float4(src[0], src[1], src[2], src[3]);
            dst[1] = make_float4(src[4], src[5], src[6], src[7]);
            dst[2] = make_float4(src[8], 0.f, 0.f, 0.f);
        }
        return;
    }

    // ---------------- prep v2 ----------------
    __shared__ float sU[RPB][10];       // Usym per job row (k-padded to 10)
    int r0 = (blockIdx.x - TRA_TILES) * RPB;
    int tid = threadIdx.x;

    // Phase A: threads 0..(RPB*10-1) each compute one Usym scalar.
    if (tid < RPB * 10) {
        int rl = tid / 10, k = tid % 10;
        int r = r0 + rl;
        float usym = 0.f;
        if (r < NJOBS) {
            int t = r / 9, m = r - t * 9;
            if (t < 9) {
                // degree-1: K=1
                if (k == 0) {
                    int i = t;
                    if (m == 0)      usym = Us1[i];
                    else if (m < 4)  usym = Up1[(m - 1) * 9 + i];
                    else             usym = Ud1[(m - 4) * 9 + i];
                }
            } else if (t < 54) {
                // degree-2
                int tp = t - 9;
                int rem = tp, i = 0, j = 0;
                for (i = 0; i < 9; i++) { int cnt = 9 - i; if (rem < cnt) { j = i + rem; break; } rem -= cnt; }
                float inv = (i == j) ? 0.5f : 1.0f;
                int K; const float* U; int mm;
                if (m == 0)      { K = 2; U = Us2; mm = 0; }
                else if (m < 4)  { K = 3; U = Up2; mm = m - 1; }
                else             { K = 4; U = Ud2; mm = m - 4; }
                if (k < K)
                    usym = (U[((mm * 9 + i) * 9 + j) * K + k] +
                            U[((mm * 9 + j) * 9 + i) * K + k]) * inv;
            } else {
                // degree-3
                int tp = t - 54;
                int rem = tp, i = 0, j = 0, l = 0;
                for (i = 0; i < 9; i++) { int cnt = (9 - i) * (10 - i) / 2; if (rem < cnt) break; rem -= cnt; }
                for (j = i; j < 9; j++) { int cnt = 9 - j; if (rem < cnt) { l = j + rem; break; } rem -= cnt; }
                float inv;
                if (i == j && j == l)                 inv = 1.0f / 6.0f;
                else if (i == j || j == l || i == l)  inv = 0.5f;
                else                                  inv = 1.0f;
                int K; const float* U; int mm;
                if (m == 0)      { K = 5;  U = Us3; mm = 0; }
                else if (m < 4)  { K = 8;  U = Up3; mm = m - 1; }
                else             { K = 10; U = Ud3; mm = m - 4; }
                if (k < K) {
                    int P0[6] = { i,i,j,j,l,l }, P1[6] = { j,l,i,l,i,j }, P2[6] = { l,j,l,i,j,i };
                    float s = 0.f;
#pragma unroll
                    for (int p = 0; p < 6; p++)
                        s += U[(((mm * 9 + P0[p]) * 9 + P1[p]) * 9 + P2[p]) * K + k];
                    usym = s * inv;
                }
            }
        }
        sU[rl][k] = usym;
    }
    __syncthreads();

    // Phase B: 256 threads = RPB rows x 128 channels.
    {
        int rl = tid >> 7;              // 0..1
        int c  = tid & 127;
        int r = r0 + rl;
        if (r >= NJOBS) return;
        int t = r / 9, m = r - t * 9;

        const float* w; int K;
        if (t < 9) {
            K = 1;
            w = (m == 0) ? ws1 : (m < 4) ? wp1 : wd1;
        } else if (t < 54) {
            if (m == 0)      { K = 2; w = ws2; }
            else if (m < 4)  { K = 3; w = wp2; }
            else             { K = 4; w = wd2; }
        } else {
            if (m == 0)      { K = 5;  w = ws3; }
            else if (m < 4)  { K = 8;  w = wp3; }
            else             { K = 10; w = wd3; }
        }

        float s = 0.f;
        for (int k = 0; k < K; k++)
            s = fmaf(sU[rl][k], w[k * NC + c], s);

        float* dst = g_S + (c * NT + t) * ROWP;
        dst[m] = s;
        if (m < 3) dst[9 + m] = 0.f;    // zero pad lanes
    }
}

// ---------------------------------------------------------------------------
// Launch 2: main (verbatim — at its FMA floor)
// ---------------------------------------------------------------------------
__device__ __forceinline__ void fma9xN(float acc[NBT][9], const float* __restrict__ row,
                                       const float mN[NBT])
{
    float4 r0 = *reinterpret_cast<const float4*>(row);
    float4 r1 = *reinterpret_cast<const float4*>(row + 4);
    float  r8 = row[8];
#pragma unroll
    for (int n = 0; n < NBT; n++) {
        acc[n][0] = fmaf(r0.x, mN[n], acc[n][0]);
        acc[n][1] = fmaf(r0.y, mN[n], acc[n][1]);
        acc[n][2] = fmaf(r0.z, mN[n], acc[n][2]);
        acc[n][3] = fmaf(r0.w, mN[n], acc[n][3]);
        acc[n][4] = fmaf(r1.x, mN[n], acc[n][4]);
        acc[n][5] = fmaf(r1.y, mN[n], acc[n][5]);
        acc[n][6] = fmaf(r1.z, mN[n], acc[n][6]);
        acc[n][7] = fmaf(r1.w, mN[n], acc[n][7]);
        acc[n][8] = fmaf(r8,  mN[n], acc[n][8]);
    }
}

__global__ __launch_bounds__(BLK) void sc_main_kernel()
{
    __shared__ __align__(16) float sS[NT * ROWP];

    int c = blockIdx.x;
    const float* gS = g_S + c * NT * ROWP;
    for (int idx = threadIdx.x; idx < NT * ROWP; idx += BLK)
        sS[idx] = gS[idx];
    __syncthreads();

    int bbase = blockIdx.y * (BLK * NBT) + threadIdx.x;

    float a[NBT][9];
#pragma unroll
    for (int n = 0; n < NBT; n++) {
        const float4* Ap = reinterpret_cast<const float4*>(
            g_At + (c * NB + bbase + n * BLK) * NIP);
        float4 v0 = Ap[0], v1 = Ap[1], v2 = Ap[2];
        a[n][0] = v0.x; a[n][1] = v0.y; a[n][2] = v0.z; a[n][3] = v0.w;
        a[n][4] = v1.x; a[n][5] = v1.y; a[n][6] = v1.z; a[n][7] = v1.w;
        a[n][8] = v2.x;
    }

    float acc[NBT][9];
#pragma unroll
    for (int n = 0; n < NBT; n++)
#pragma unroll
        for (int q = 0; q < 9; q++) acc[n][q] = 0.f;

#pragma unroll
    for (int i = 0; i < 9; i++) {
        float mN[NBT];
#pragma unroll
        for (int n = 0; n < NBT; n++) mN[n] = a[n][i];
        fma9xN(acc, sS + i * ROWP, mN);
    }

    int trow = 54;
#pragma unroll
    for (int i = 0; i < 9; i++) {
#pragma unroll
        for (int j = i; j < 9; j++) {
            int pidx = i * 9 - (i * (i - 1)) / 2 + (j - i);
            float pN[NBT];
#pragma unroll
            for (int n = 0; n < NBT; n++) pN[n] = a[n][i] * a[n][j];
            fma9xN(acc, sS + (9 + pidx) * ROWP, pN);
#pragma unroll
            for (int l = j; l < 9; l++) {
                float mN[NBT];
#pragma unroll
                for (int n = 0; n < NBT; n++) mN[n] = pN[n] * a[n][l];
                fma9xN(acc, sS + trow * ROWP, mN);
                trow++;
            }
        }
    }

#pragma unroll
    for (int n = 0; n < NBT; n++) {
        float4* op = reinterpret_cast<float4*>(
            g_Ot + (c * NB + bbase + n * BLK) * NIP);
        op[0] = make_float4(acc[n][0], acc[n][1], acc[n][2], acc[n][3]);
        op[1] = make_float4(acc[n][4], acc[n][5], acc[n][6], acc[n][7]);
        op[2] = make_float4(acc[n][8], 0.f, 0.f, 0.f);
    }
}

// ---------------------------------------------------------------------------
// Launch 3: trO (verbatim R10)
// ---------------------------------------------------------------------------
__global__ __launch_bounds__(256) void trO_kernel(float* __restrict__ out)
{
    __shared__ float tile[TRB * TP];

    int bt = blockIdx.x >> 2;
    int ct = blockIdx.x & 3;
    int b0 = bt * TRB, c0 = ct * TRC;
    int tid = threadIdx.x;

#pragma unroll
    for (int it = 0; it < (TRB * TRC) / 256; it++) {
        int pair = it * 256 + tid;
        int cc = pair >> 5, b = pair & 31;
        const float4* src = reinterpret_cast<const float4*>(
            g_Ot + ((c0 + cc) * NB + b0 + b) * NIP);
        float4 v0 = src[0], v1 = src[1], v2 = src[2];
        float* t = tile + b * TP + cc * NI;
        t[0] = v0.x; t[1] = v0.y; t[2] = v0.z; t[3] = v0.w;
        t[4] = v1.x; t[5] = v1.y; t[6] = v1.z; t[7] = v1.w;
        t[8] = v2.x;
    }
    __syncthreads();

#pragma unroll
    for (int v = tid; v < TILE_WORDS; v += 256) {
        int b = v / (TRC * NI), q = v - b * (TRC * NI);
        out[(b0 + b) * (NC * NI) + c0 * NI + q] = tile[b * TP + q];
    }
}

// ---------------------------------------------------------------------------
// Launch
// ---------------------------------------------------------------------------
extern "C" void kernel_launch(void* const* d_in, const int* in_sizes, int n_in,
                              void* d_out, int out_size)
{
    const float* A = nullptr;
    const float* U[3][3] = {};
    const float* W[3][3] = {};

    int typeorder[3] = { 0, 1, 2 };
    int to_n = 0;
    int w1_idx[3]; int w1_n = 0;

    for (int idx = 0; idx < n_in; idx++) {
        int s = in_sizes[idx];
        const float* p = (const float*)d_in[idx];
        switch (s) {
            case NB * NC * NI: A = p; break;
            case 9:     U[0][0] = p; break;
            case 162:   U[0][1] = p; break;
            case 3645:  U[0][2] = p; break;
            case 27:    U[1][0] = p; break;
            case 729:   U[1][1] = p; break;
            case 17496: U[1][2] = p; break;
            case 45:    U[2][0] = p; break;
            case 1620:  U[2][1] = p; break;
            case 36450: U[2][2] = p; break;
            case 256:   W[0][1] = p; if (to_n < 3) typeorder[to_n++] = 0; break;
            case 384:   W[1][1] = p; if (to_n < 3) typeorder[to_n++] = 1; break;
            case 512:   W[2][1] = p; if (to_n < 3) typeorder[to_n++] = 2; break;
            case 640:   W[0][2] = p; break;
            case 1024:  W[1][2] = p; break;
            case 1280:  W[2][2] = p; break;
            case 128:   if (w1_n < 3) w1_idx[w1_n++] = idx; break;
            default: break;
        }
    }
    for (int q = 0; q < 3 && q < w1_n; q++)
        W[typeorder[q]][0] = (const float*)d_in[w1_idx[q]];

    // Launch 1: fused trA + prep v2
    pre_kernel<<<TRA_TILES + PREP_BLOCKS, 256>>>(
        A,
        U[0][0], U[1][0], U[2][0],
        U[0][1], U[1][1], U[2][1],
        U[0][2], U[1][2], U[2][2],
        W[0][0], W[0][1], W[0][2],
        W[1][0], W[1][1], W[1][2],
        W[2][0], W[2][1], W[2][2]);

    // Launch 2: main
    {
        dim3 grid(NC, NB / (BLK * NBT));
        sc_main_kernel<<<grid, BLK>>>();
    }

    // Launch 3: trO
    trO_kernel<<<TRA_TILES, 256>>>((float*)d_out);
}

// round 12
// speedup vs baseline: 1.5275x; 1.2381x over previous
#include <cuda_runtime.h>

// ---------------------------------------------------------------------------
// SymmetricContraction: out[b,c,m] = cubic polynomial in A[b,c,0..8]
// Launch 1 (prep):  S[c][t][m] = sum_k Usym[t][m][k] * w_k[c]  (g_S)
// Launch 2 (main):  fully fused. 256 thr = 8 warps; warp -> channel c0+(w&3),
//   (w>>2) -> node half. 4 S-tables (flat float4 fill) + A tile staged in smem.
//   Math in packed f32x2 (dual-FP32): acc = 5 pairs over m, rows read as
//   ulonglong2 pairs, mono duplicated per node.
// ---------------------------------------------------------------------------

#define NC 128
#define NB 2048
#define NI 9
#define NT 219
#define ROWP 12
#define TBLW (NT * ROWP)          // 2628 floats per channel table
#define CPB 4                     // channels per block
#define NPB 128                   // nodes per block
#define TS 37                     // tile row stride (odd)
#define SM_FLOATS (CPB * TBLW + NPB * TS)     // 10512 + 4736 = 15248
#define SMEM_BYTES (SM_FLOATS * 4)            // 60992

#define NJOBS (NT * 9)
#define RPB 2
#define PREP_BLOCKS ((NJOBS + RPB - 1) / RPB)  // 986

static __device__ float g_S[NC * TBLW];

typedef unsigned long long u64;

__device__ __forceinline__ u64 dup2(float x) {
    u64 r; unsigned xi = __float_as_uint(x);
    asm("mov.b64 %0, {%1, %1};" : "=l"(r) : "r"(xi));
    return r;
}
__device__ __forceinline__ u64 fma2(u64 a, u64 b, u64 c) {
    u64 r;
    asm("fma.rn.f32x2 %0, %1, %2, %3;" : "=l"(r) : "l"(a), "l"(b), "l"(c));
    return r;
}
__device__ __forceinline__ void unpack2(u64 v, float& lo, float& hi) {
    unsigned l_, h_;
    asm("mov.b64 {%0, %1}, %2;" : "=r"(l_), "=r"(h_) : "l"(v));
    lo = __uint_as_float(l_); hi = __uint_as_float(h_);
}

// ---------------------------------------------------------------------------
// Launch 1: prep (verified R11 logic, standalone)
// ---------------------------------------------------------------------------
__global__ __launch_bounds__(256) void prep_kernel(
    const float* __restrict__ Us1, const float* __restrict__ Up1, const float* __restrict__ Ud1,
    const float* __restrict__ Us2, const float* __restrict__ Up2, const float* __restrict__ Ud2,
    const float* __restrict__ Us3, const float* __restrict__ Up3, const float* __restrict__ Ud3,
    const float* __restrict__ ws1, const float* __restrict__ ws2, const float* __restrict__ ws3,
    const float* __restrict__ wp1, const float* __restrict__ wp2, const float* __restrict__ wp3,
    const float* __restrict__ wd1, const float* __restrict__ wd2, const float* __restrict__ wd3)
{
    __shared__ float sU[RPB][10];
    int r0 = blockIdx.x * RPB;
    int tid = threadIdx.x;

    if (tid < RPB * 10) {
        int rl = tid / 10, k = tid % 10;
        int r = r0 + rl;
        float usym = 0.f;
        if (r < NJOBS) {
            int t = r / 9, m = r - t * 9;
            if (t < 9) {
                if (k == 0) {
                    int i = t;
                    if (m == 0)      usym = Us1[i];
                    else if (m < 4)  usym = Up1[(m - 1) * 9 + i];
                    else             usym = Ud1[(m - 4) * 9 + i];
                }
            } else if (t < 54) {
                int tp = t - 9;
                int rem = tp, i = 0, j = 0;
                for (i = 0; i < 9; i++) { int cnt = 9 - i; if (rem < cnt) { j = i + rem; break; } rem -= cnt; }
                float inv = (i == j) ? 0.5f : 1.0f;
                int K; const float* U; int mm;
                if (m == 0)      { K = 2; U = Us2; mm = 0; }
                else if (m < 4)  { K = 3; U = Up2; mm = m - 1; }
                else             { K = 4; U = Ud2; mm = m - 4; }
                if (k < K)
                    usym = (U[((mm * 9 + i) * 9 + j) * K + k] +
                            U[((mm * 9 + j) * 9 + i) * K + k]) * inv;
            } else {
                int tp = t - 54;
                int rem = tp, i = 0, j = 0, l = 0;
                for (i = 0; i < 9; i++) { int cnt = (9 - i) * (10 - i) / 2; if (rem < cnt) break; rem -= cnt; }
                for (j = i; j < 9; j++) { int cnt = 9 - j; if (rem < cnt) { l = j + rem; break; } rem -= cnt; }
                float inv;
                if (i == j && j == l)                 inv = 1.0f / 6.0f;
                else if (i == j || j == l || i == l)  inv = 0.5f;
                else                                  inv = 1.0f;
                int K; const float* U; int mm;
                if (m == 0)      { K = 5;  U = Us3; mm = 0; }
                else if (m < 4)  { K = 8;  U = Up3; mm = m - 1; }
                else             { K = 10; U = Ud3; mm = m - 4; }
                if (k < K) {
                    int P0[6] = { i,i,j,j,l,l }, P1[6] = { j,l,i,l,i,j }, P2[6] = { l,j,l,i,j,i };
                    float s = 0.f;
#pragma unroll
                    for (int p = 0; p < 6; p++)
                        s += U[(((mm * 9 + P0[p]) * 9 + P1[p]) * 9 + P2[p]) * K + k];
                    usym = s * inv;
                }
            }
        }
        sU[rl][k] = usym;
    }
    __syncthreads();

    {
        int rl = tid >> 7;
        int c  = tid & 127;
        int r = r0 + rl;
        if (r >= NJOBS) return;
        int t = r / 9, m = r - t * 9;

        const float* w; int K;
        if (t < 9) {
            K = 1;
            w = (m == 0) ? ws1 : (m < 4) ? wp1 : wd1;
        } else if (t < 54) {
            if (m == 0)      { K = 2; w = ws2; }
            else if (m < 4)  { K = 3; w = wp2; }
            else             { K = 4; w = wd2; }
        } else {
            if (m == 0)      { K = 5;  w = ws3; }
            else if (m < 4)  { K = 8;  w = wp3; }
            else             { K = 10; w = wd3; }
        }

        float s = 0.f;
        for (int k = 0; k < K; k++)
            s = fmaf(sU[rl][k], w[k * NC + c], s);

        float* dst = g_S + c * TBLW + t * ROWP;
        dst[m] = s;
        if (m < 3) dst[9 + m] = 0.f;   // row pads (row[9] load-bearing for f32x2)
    }
}

// ---------------------------------------------------------------------------
// Launch 2: fused main
// ---------------------------------------------------------------------------
__device__ __forceinline__ void fmarow(u64 acc0[5], u64 acc1[5],
                                       const float* __restrict__ row,
                                       float m0, float m1)
{
    u64 d0 = dup2(m0), d1 = dup2(m1);
    ulonglong2 ra = *reinterpret_cast<const ulonglong2*>(row);       // (r0,r1)(r2,r3)
    ulonglong2 rb = *reinterpret_cast<const ulonglong2*>(row + 4);   // (r4,r5)(r6,r7)
    u64 rc = *reinterpret_cast<const u64*>(row + 8);                 // (r8, 0)
    acc0[0] = fma2(ra.x, d0, acc0[0]);  acc1[0] = fma2(ra.x, d1, acc1[0]);
    acc0[1] = fma2(ra.y, d0, acc0[1]);  acc1[1] = fma2(ra.y, d1, acc1[1]);
    acc0[2] = fma2(rb.x, d0, acc0[2]);  acc1[2] = fma2(rb.x, d1, acc1[2]);
    acc0[3] = fma2(rb.y, d0, acc0[3]);  acc1[3] = fma2(rb.y, d1, acc1[3]);
    acc0[4] = fma2(rc,   d0, acc0[4]);  acc1[4] = fma2(rc,   d1, acc1[4]);
}

__global__ __launch_bounds__(256) void sc_main_kernel(
    const float* __restrict__ A, float* __restrict__ out)
{
    extern __shared__ __align__(16) float smem[];
    float* sT = smem;                    // [CPB][TBLW]
    float* sA = smem + CPB * TBLW;       // [NPB][TS], reused for output

    int c0 = blockIdx.x * CPB;
    int b0 = blockIdx.y * NPB;
    int tid = threadIdx.x;
    int w4 = (tid >> 5) & 3;             // channel within block
    int half = tid >> 7;                 // node half
    int lane = tid & 31;

    // ---- fill tables: flat float4 copy (deep MLP, no serial chains)
    {
        const float4* src4 = reinterpret_cast<const float4*>(g_S + c0 * TBLW);
        float4* dst4 = reinterpret_cast<float4*>(sT);
#pragma unroll 4
        for (int v = tid; v < (CPB * TBLW) / 4; v += 256)
            dst4[v] = src4[v];
    }

    // ---- fill A tile: 128 runs of 36 contiguous floats
#pragma unroll 4
    for (int v = tid; v < NPB * 36; v += 256) {
        int b = v / 36, q = v - b * 36;
        sA[b * TS + q] = A[(b0 + b) * (NC * NI) + c0 * NI + q];
    }
    __syncthreads();

    // ---- per-thread a vectors (stride-37 LDS, conflict-free)
    int row0 = half * 64 + lane;
    float a0[9], a1[9];
    {
        const float* p0 = sA + row0 * TS + w4 * NI;
        const float* p1 = sA + (row0 + 32) * TS + w4 * NI;
#pragma unroll
        for (int i = 0; i < 9; i++) { a0[i] = p0[i]; a1[i] = p1[i]; }
    }
    __syncthreads();   // tile reads complete before epilogue overwrite

    const float* tbl = sT + w4 * TBLW;

    u64 acc0[5], acc1[5];
#pragma unroll
    for (int q = 0; q < 5; q++) { acc0[q] = 0ull; acc1[q] = 0ull; }

    // ---- degree 1
#pragma unroll
    for (int i = 0; i < 9; i++)
        fmarow(acc0, acc1, tbl + i * ROWP, a0[i], a1[i]);

    // ---- degree 2 + 3
    int trow = 54;
#pragma unroll
    for (int i = 0; i < 9; i++) {
#pragma unroll
        for (int j = i; j < 9; j++) {
            int pidx = i * 9 - (i * (i - 1)) / 2 + (j - i);
            float p0 = a0[i] * a0[j];
            float p1 = a1[i] * a1[j];
            fmarow(acc0, acc1, tbl + (9 + pidx) * ROWP, p0, p1);
#pragma unroll
            for (int l = j; l < 9; l++) {
                fmarow(acc0, acc1, tbl + trow * ROWP, p0 * a0[l], p1 * a1[l]);
                trow++;
            }
        }
    }

    // ---- stage results into tile, then coalesced flush
    {
        float* o0 = sA + row0 * TS + w4 * NI;
        float* o1 = sA + (row0 + 32) * TS + w4 * NI;
#pragma unroll
        for (int q = 0; q < 4; q++) {
            float lo, hi;
            unpack2(acc0[q], lo, hi); o0[2 * q] = lo; o0[2 * q + 1] = hi;
            unpack2(acc1[q], lo, hi); o1[2 * q] = lo; o1[2 * q + 1] = hi;
        }
        float lo, hi;
        unpack2(acc0[4], lo, hi); o0[8] = lo;
        unpack2(acc1[4], lo, hi); o1[8] = lo;
    }
    __syncthreads();

#pragma unroll 4
    for (int v = tid; v < NPB * 36; v += 256) {
        int b = v / 36, q = v - b * 36;
        out[(b0 + b) * (NC * NI) + c0 * NI + q] = sA[b * TS + q];
    }
}

// ---------------------------------------------------------------------------
// Launch
// ---------------------------------------------------------------------------
extern "C" void kernel_launch(void* const* d_in, const int* in_sizes, int n_in,
                              void* d_out, int out_size)
{
    const float* A = nullptr;
    const float* U[3][3] = {};
    const float* W[3][3] = {};

    int typeorder[3] = { 0, 1, 2 };
    int to_n = 0;
    int w1_idx[3]; int w1_n = 0;

    for (int idx = 0; idx < n_in; idx++) {
        int s = in_sizes[idx];
        const float* p = (const float*)d_in[idx];
        switch (s) {
            case NB * NC * NI: A = p; break;
            case 9:     U[0][0] = p; break;
            case 162:   U[0][1] = p; break;
            case 3645:  U[0][2] = p; break;
            case 27:    U[1][0] = p; break;
            case 729:   U[1][1] = p; break;
            case 17496: U[1][2] = p; break;
            case 45:    U[2][0] = p; break;
            case 1620:  U[2][1] = p; break;
            case 36450: U[2][2] = p; break;
            case 256:   W[0][1] = p; if (to_n < 3) typeorder[to_n++] = 0; break;
            case 384:   W[1][1] = p; if (to_n < 3) typeorder[to_n++] = 1; break;
            case 512:   W[2][1] = p; if (to_n < 3) typeorder[to_n++] = 2; break;
            case 640:   W[0][2] = p; break;
            case 1024:  W[1][2] = p; break;
            case 1280:  W[2][2] = p; break;
            case 128:   if (w1_n < 3) w1_idx[w1_n++] = idx; break;
            default: break;
        }
    }
    for (int q = 0; q < 3 && q < w1_n; q++)
        W[typeorder[q]][0] = (const float*)d_in[w1_idx[q]];

    static bool attr_done = false;
    if (!attr_done) {
        cudaFuncSetAttribute(sc_main_kernel,
                             cudaFuncAttributeMaxDynamicSharedMemorySize, SMEM_BYTES);
        attr_done = true;
    }

    // Launch 1: prep
    prep_kernel<<<PREP_BLOCKS, 256>>>(
        U[0][0], U[1][0], U[2][0],
        U[0][1], U[1][1], U[2][1],
        U[0][2], U[1][2], U[2][2],
        W[0][0], W[0][1], W[0][2],
        W[1][0], W[1][1], W[1][2],
        W[2][0], W[2][1], W[2][2]);

    // Launch 2: fused main
    {
        dim3 grid(NC / CPB, NB / NPB);   // (32, 16)
        sc_main_kernel<<<grid, 256, SMEM_BYTES>>>(A, (float*)d_out);
    }
}